// round 10
// baseline (speedup 1.0000x reference)
#include <cuda_runtime.h>

#define THREADS 256
#define DPB 512              // dims per block
#define NBINS 16

__device__ float g_partials[32768];
__device__ unsigned int g_counter = 0;

// Scalar fallback for tail dims (not used when dim % 512 == 0).
__device__ float ep_scalar_dim(const float* __restrict__ obs,
                               const float* __restrict__ counts,
                               float* __restrict__ out,
                               int dim, int rows, float inv_rows, int i)
{
    float m = 0.0f;
    for (int r = 0; r < rows; ++r) m += obs[(size_t)r * dim + i];
    m *= inv_rows;
    float sgm = 1.0f / (1.0f + __expf(-m));
    int b = (int)(sgm * (float)(NBINS - 1));
    b = b < 0 ? 0 : (b > NBINS - 1 ? NBINS - 1 : b);

    float c[NBINS];
    #pragma unroll
    for (int j = 0; j < NBINS; ++j) c[j] = counts[(size_t)i * NBINS + j];
    float s = 0.0f;
    #pragma unroll
    for (int j = 0; j < NBINS; ++j) s += c[j];
    float inv  = 1.0f / fmaxf(s,        1e-8f);
    float invp = 1.0f / fmaxf(s + 1.0f, 1e-8f);
    float Hp = 0.0f, Hq = 0.0f, ig = 0.0f;
    #pragma unroll
    for (int j = 0; j < NBINS; ++j) {
        float oh = (j == b) ? 1.0f : 0.0f;
        float p  = c[j] * inv;
        float pp = (c[j] + oh) * invp;
        float lp = __log2f(p  + 1e-10f);
        float lq = __log2f(pp + 1e-10f);
        Hp -= p * lp; Hq -= pp * lq;
        ig += pp * (lq - lp);
        out[(size_t)3 * dim + 2 + (size_t)i * NBINS + j] =
            fmaxf(c[j] * 0.95f + oh * 0.05f, 0.01f);
    }
    ig = fmaxf(ig, 0.0f);
    out[i] = ig;
    out[(size_t)dim     + 1 + i] = Hp;
    out[(size_t)2 * dim + 1 + i] = Hq;
    return ig;
}

__global__ void __launch_bounds__(THREADS, 5) ep_fused_kernel(
    const float* __restrict__ obs,      // (rows, dim)
    const float* __restrict__ counts,   // (dim, 16)
    float* __restrict__ out,            // concatenated outputs
    int dim, int rows, float inv_rows, int nblocks)
{
    // Padded staging: local dim d owns float4 slots [d*5, d*5+4); slot d*5+4
    // is padding (conflict-free LDS.128 per-row reads).
    __shared__ float4 s4[DPB * 5];      // 40 KB
    __shared__ int    sb[DPB];          // bin per local dim
    float2* s2 = (float2*)s4;

    const int t    = threadIdx.x;
    const int base = blockIdx.x * DPB;
    const bool full = (base + DPB <= dim);   // uniform per block

    float igacc = 0.0f;

    if (full) {
        // ============ front-batched loads (max MLP) ============
        const float4* cin = (const float4*)counts + (size_t)base * 4;
        // Phase-A dims for this thread: base+2t, base+2t+1 (float2 obs loads)
        const float2* op2 = (const float2*)(obs + base) + t;
        const int halfdim = dim >> 1;

        float4 cv0, cv1, cv2, cv3, cv4, cv5, cv6, cv7;
        float m0, m1;
        if (rows == 8) {
            float2 o0 = __ldcs(op2);
            float2 o1 = __ldcs(op2 +     halfdim);
            float2 o2 = __ldcs(op2 + 2 * halfdim);
            float2 o3 = __ldcs(op2 + 3 * halfdim);
            float2 o4 = __ldcs(op2 + 4 * halfdim);
            float2 o5 = __ldcs(op2 + 5 * halfdim);
            float2 o6 = __ldcs(op2 + 6 * halfdim);
            float2 o7 = __ldcs(op2 + 7 * halfdim);
            cv0 = __ldcs(cin + t);
            cv1 = __ldcs(cin + t +     THREADS);
            cv2 = __ldcs(cin + t + 2 * THREADS);
            cv3 = __ldcs(cin + t + 3 * THREADS);
            cv4 = __ldcs(cin + t + 4 * THREADS);
            cv5 = __ldcs(cin + t + 5 * THREADS);
            cv6 = __ldcs(cin + t + 6 * THREADS);
            cv7 = __ldcs(cin + t + 7 * THREADS);
            m0 = (((o0.x + o1.x) + (o2.x + o3.x)) +
                  ((o4.x + o5.x) + (o6.x + o7.x))) * inv_rows;
            m1 = (((o0.y + o1.y) + (o2.y + o3.y)) +
                  ((o4.y + o5.y) + (o6.y + o7.y))) * inv_rows;
        } else {
            m0 = 0.0f; m1 = 0.0f;
            for (int r = 0; r < rows; ++r) {
                float2 o = __ldcs(op2 + (size_t)r * halfdim);
                m0 += o.x; m1 += o.y;
            }
            m0 *= inv_rows; m1 *= inv_rows;
            cv0 = __ldcs(cin + t);
            cv1 = __ldcs(cin + t +     THREADS);
            cv2 = __ldcs(cin + t + 2 * THREADS);
            cv3 = __ldcs(cin + t + 3 * THREADS);
            cv4 = __ldcs(cin + t + 4 * THREADS);
            cv5 = __ldcs(cin + t + 5 * THREADS);
            cv6 = __ldcs(cin + t + 6 * THREADS);
            cv7 = __ldcs(cin + t + 7 * THREADS);
        }

        // stage counts -> padded smem (coalesced-in, conflict-free pattern)
        {
            int j0 = t;
            s4[((j0              ) >> 2) * 5 + (j0 & 3)] = cv0;
            s4[((j0 +     THREADS) >> 2) * 5 + (j0 & 3)] = cv1;
            s4[((j0 + 2 * THREADS) >> 2) * 5 + (j0 & 3)] = cv2;
            s4[((j0 + 3 * THREADS) >> 2) * 5 + (j0 & 3)] = cv3;
            s4[((j0 + 4 * THREADS) >> 2) * 5 + (j0 & 3)] = cv4;
            s4[((j0 + 5 * THREADS) >> 2) * 5 + (j0 & 3)] = cv5;
            s4[((j0 + 6 * THREADS) >> 2) * 5 + (j0 & 3)] = cv6;
            s4[((j0 + 7 * THREADS) >> 2) * 5 + (j0 & 3)] = cv7;
        }

        // sigmoid binning for phase-A dims (overlaps smem drain)
        {
            float sg0 = 1.0f / (1.0f + __expf(-m0));
            float sg1 = 1.0f / (1.0f + __expf(-m1));
            int b0 = (int)(sg0 * (float)(NBINS - 1));
            int b1 = (int)(sg1 * (float)(NBINS - 1));
            b0 = b0 < 0 ? 0 : (b0 > NBINS - 1 ? NBINS - 1 : b0);
            b1 = b1 < 0 ? 0 : (b1 > NBINS - 1 ? NBINS - 1 : b1);
            sb[2 * t]     = b0;
            sb[2 * t + 1] = b1;
        }

        __syncthreads();   // s4 + sb block-visible

        // ============ compute phase: local dims t and t+256 ============
        #pragma unroll
        for (int e = 0; e < 2; ++e) {
            const int ld = t + e * THREADS;     // local dim
            const int i  = base + ld;           // global dim
            const int b  = sb[ld];

            float c[NBINS];
            #pragma unroll
            for (int q = 0; q < 4; ++q) {
                float4 v = s4[ld * 5 + q];
                c[4*q+0] = v.x; c[4*q+1] = v.y; c[4*q+2] = v.z; c[4*q+3] = v.w;
            }

            float s = 0.0f;
            #pragma unroll
            for (int j = 0; j < NBINS; ++j) s += c[j];

            // log2(c/s + 1e-10) = log2(c + 1e-10*s) - log2(s)  (exact)
            const float tiny = 1e-10f * s;
            float T = 0.0f, cb = 0.0f, ubin = 0.0f;
            #pragma unroll
            for (int j = 0; j < NBINS; ++j) {
                float u = __log2f(c[j] + tiny);
                T += c[j] * u;
                if (j == b) { cb = c[j]; ubin = u; }
            }
            float ub  = __log2f(cb + 1.0f);
            float ls  = __log2f(s);
            float ls1 = __log2f(s + 1.0f);
            float inv  = 1.0f / s;
            float invp = 1.0f / (s + 1.0f);

            float Hp = ls  - T * inv;
            float Hq = ls1 - (T - cb * ubin + (cb + 1.0f) * ub) * invp;
            float ig = fmaxf((cb + 1.0f) * invp * (ub - ubin) - (ls1 - ls), 0.0f);

            __stcs(out + i, ig);
            __stcs(out + (size_t)dim     + 1 + i, Hp);
            __stcs(out + (size_t)2 * dim + 1 + i, Hq);
            igacc += ig;
        }

        // ============ coalesced new_counts stage-out ============
        // DPB*16 floats = DPB*8 = 4096 float2 slots -> 16 iterations of 256.
        float2* obase = (float2*)(out + (size_t)3 * dim + 2 + (size_t)base * NBINS);
        #pragma unroll
        for (int k = 0; k < 16; ++k) {
            int idx = t + k * THREADS;                 // float2 idx [0, 4096)
            int d = idx >> 3, h = idx & 7;
            float2 cc = s2[d * 10 + h];
            int bd = sb[d];
            float o0 = (2 * h     == bd) ? 0.05f : 0.0f;
            float o1 = (2 * h + 1 == bd) ? 0.05f : 0.0f;
            float2 r;
            r.x = fmaxf(cc.x * 0.95f + o0, 0.01f);
            r.y = fmaxf(cc.y * 0.95f + o1, 0.01f);
            __stcs(obase + idx, r);
        }
    } else {
        // ---- scalar tail (not taken when dim % 512 == 0) ----
        int i0 = base + t;
        if (i0 < dim)
            igacc += ep_scalar_dim(obs, counts, out, dim, rows, inv_rows, i0);
        int i1 = base + t + THREADS;
        if (i1 < dim)
            igacc += ep_scalar_dim(obs, counts, out, dim, rows, inv_rows, i1);
    }

    // ---- deterministic block reduction of igacc ----
    const unsigned FULL_M = 0xffffffffu;
    #pragma unroll
    for (int o = 16; o > 0; o >>= 1)
        igacc += __shfl_down_sync(FULL_M, igacc, o);

    __shared__ float ws[THREADS / 32];
    int lane = t & 31;
    int w    = t >> 5;
    if (lane == 0) ws[w] = igacc;
    __syncthreads();
    if (w == 0) {
        float v = (lane < THREADS / 32) ? ws[lane] : 0.0f;
        #pragma unroll
        for (int o = 4; o > 0; o >>= 1)
            v += __shfl_down_sync(FULL_M, v, o);
        if (lane == 0) g_partials[blockIdx.x] = v;
    }

    // ---- last-block final reduction ----
    __shared__ bool is_last;
    __threadfence();
    if (t == 0) {
        unsigned ticket = atomicAdd(&g_counter, 1u);
        is_last = (ticket == (unsigned)(nblocks - 1));
    }
    __syncthreads();

    if (is_last) {
        __threadfence();
        __shared__ double sh[THREADS];
        double a = 0.0;
        for (int p = t; p < nblocks; p += THREADS)   // fixed order
            a += (double)g_partials[p];
        sh[t] = a;
        __syncthreads();
        #pragma unroll
        for (int o = THREADS / 2; o > 0; o >>= 1) {
            if (t < o) sh[t] += sh[t + o];
            __syncthreads();
        }
        if (t == 0) {
            float mean = (float)(sh[0] / (double)dim);
            out[dim] = mean;
            float z = mean * 50.0f - 1.0f;
            out[(size_t)3 * dim + 1] = 1.0f / (1.0f + expf(-z));
            g_counter = 0;   // reset for next graph replay
        }
    }
}

extern "C" void kernel_launch(void* const* d_in, const int* in_sizes, int n_in,
                              void* d_out, int out_size)
{
    const float* obs    = (const float*)d_in[0];
    const float* counts = (const float*)d_in[1];
    float* out = (float*)d_out;

    int dim  = in_sizes[1] / NBINS;
    int rows = in_sizes[0] / dim;
    int nb   = (dim + DPB - 1) / DPB;

    ep_fused_kernel<<<nb, THREADS>>>(obs, counts, out, dim, rows,
                                     1.0f / (float)rows, nb);
}

// round 13
// speedup vs baseline: 1.0889x; 1.0889x over previous
#include <cuda_runtime.h>

#define THREADS 256
#define NBINS 16

__device__ float g_partials[32768];
__device__ unsigned int g_counter = 0;

__global__ void __launch_bounds__(THREADS, 7) ep_fused_kernel(
    const float* __restrict__ obs,      // (rows, dim)
    const float* __restrict__ counts,   // (dim, 16)
    float* __restrict__ out,            // concatenated outputs
    int dim, int rows, float inv_rows, int nblocks)
{
    // Padded staging: local dim d owns float4 slots [d*5, d*5+4); slot d*5+4
    // is padding (conflict-free LDS.128 per-row reads).
    __shared__ float4 s4[THREADS * 5];   // 20 KB
    __shared__ int    sb[THREADS];
    float2* s2 = (float2*)s4;

    const int t    = threadIdx.x;
    const int base = blockIdx.x * THREADS;
    const int i    = base + t;
    const bool full = (base + THREADS <= dim);   // uniform per block

    float ig = 0.0f;

    if (full) {
        // ================= front-batched loads (max MLP) =================
        const float* op = obs + i;
        const float4* cin = (const float4*)counts + (size_t)base * 4;

        float m;
        float4 cv0, cv1, cv2, cv3;
        if (rows == 8) {
            // 8 obs LDG.32 + 4 counts LDG.128 issued back-to-back
            float o0 = __ldcs(op);
            float o1 = __ldcs(op + (size_t)dim);
            float o2 = __ldcs(op + (size_t)2 * dim);
            float o3 = __ldcs(op + (size_t)3 * dim);
            float o4 = __ldcs(op + (size_t)4 * dim);
            float o5 = __ldcs(op + (size_t)5 * dim);
            float o6 = __ldcs(op + (size_t)6 * dim);
            float o7 = __ldcs(op + (size_t)7 * dim);
            cv0 = __ldcs(cin + t);
            cv1 = __ldcs(cin + t + THREADS);
            cv2 = __ldcs(cin + t + 2 * THREADS);
            cv3 = __ldcs(cin + t + 3 * THREADS);
            m = (((o0 + o1) + (o2 + o3)) + ((o4 + o5) + (o6 + o7))) * inv_rows;
        } else {
            m = 0.0f;
            for (int r = 0; r < rows; ++r) m += __ldcs(op + (size_t)r * dim);
            m *= inv_rows;
            cv0 = __ldcs(cin + t);
            cv1 = __ldcs(cin + t + THREADS);
            cv2 = __ldcs(cin + t + 2 * THREADS);
            cv3 = __ldcs(cin + t + 3 * THREADS);
        }

        // stage counts -> padded smem (coalesced-in, conflict-free rows)
        {
            int idx0 = t;
            int idx1 = t + THREADS;
            int idx2 = t + 2 * THREADS;
            int idx3 = t + 3 * THREADS;
            s4[(idx0 >> 2) * 5 + (idx0 & 3)] = cv0;
            s4[(idx1 >> 2) * 5 + (idx1 & 3)] = cv1;
            s4[(idx2 >> 2) * 5 + (idx2 & 3)] = cv2;
            s4[(idx3 >> 2) * 5 + (idx3 & 3)] = cv3;
        }

        // sigmoid binning (overlaps smem drain)
        float sgm = 1.0f / (1.0f + __expf(-m));
        int b = (int)(sgm * (float)(NBINS - 1));
        b = b < 0 ? 0 : (b > NBINS - 1 ? NBINS - 1 : b);
        sb[t] = b;

        __syncthreads();   // single barrier: s4 + sb now block-visible

        // ---- own counts row from smem (conflict-free LDS.128 x4) ----
        float c[NBINS];
        #pragma unroll
        for (int q = 0; q < 4; ++q) {
            float4 v = s4[t * 5 + q];
            c[4*q+0] = v.x; c[4*q+1] = v.y; c[4*q+2] = v.z; c[4*q+3] = v.w;
        }

        float s = 0.0f;
        #pragma unroll
        for (int j = 0; j < NBINS; ++j) s += c[j];

        // Exact decomposition: log2(c/s + 1e-10) = log2(c + 1e-10*s) - log2(s)
        const float tiny = 1e-10f * s;
        float T = 0.0f, cb = 0.0f, ubin = 0.0f;
        #pragma unroll
        for (int j = 0; j < NBINS; ++j) {
            float u = __log2f(c[j] + tiny);
            T += c[j] * u;
            if (j == b) { cb = c[j]; ubin = u; }
        }
        float ub  = __log2f(cb + 1.0f);
        float ls  = __log2f(s);
        float ls1 = __log2f(s + 1.0f);
        float inv  = 1.0f / s;
        float invp = 1.0f / (s + 1.0f);

        float Hp = ls  - T * inv;
        float Hq = ls1 - (T - cb * ubin + (cb + 1.0f) * ub) * invp;
        ig = fmaxf((cb + 1.0f) * invp * (ub - ubin) - (ls1 - ls), 0.0f);

        __stcs(out + i, ig);
        __stcs(out + (size_t)dim     + 1 + i, Hp);
        __stcs(out + (size_t)2 * dim + 1 + i, Hq);

        // ---- coalesced new_counts stores from input staging ----
        // 256 dims * 16 floats = 2048 float2 slots -> 8 iterations of 256.
        float2* obase = (float2*)(out + (size_t)3 * dim + 2 + (size_t)base * NBINS);
        #pragma unroll
        for (int k = 0; k < 8; ++k) {
            int idx = t + k * THREADS;                 // float2 idx [0, 2048)
            int d = idx >> 3, h = idx & 7;
            float2 cc = s2[d * 10 + h];
            int bd = sb[d];
            float o0 = (2 * h     == bd) ? 0.05f : 0.0f;
            float o1 = (2 * h + 1 == bd) ? 0.05f : 0.0f;
            float2 r;
            r.x = fmaxf(cc.x * 0.95f + o0, 0.01f);
            r.y = fmaxf(cc.y * 0.95f + o1, 0.01f);
            __stcs(obase + idx, r);
        }
    } else if (i < dim) {
        // ---- scalar tail (not taken when dim % 256 == 0) ----
        float m = 0.0f;
        for (int r = 0; r < rows; ++r) m += obs[(size_t)r * dim + i];
        m *= inv_rows;
        float sgm = 1.0f / (1.0f + __expf(-m));
        int b = (int)(sgm * (float)(NBINS - 1));
        b = b < 0 ? 0 : (b > NBINS - 1 ? NBINS - 1 : b);

        float c[NBINS];
        #pragma unroll
        for (int j = 0; j < NBINS; ++j) c[j] = counts[(size_t)i * NBINS + j];
        float s = 0.0f;
        #pragma unroll
        for (int j = 0; j < NBINS; ++j) s += c[j];
        float inv  = 1.0f / fmaxf(s,        1e-8f);
        float invp = 1.0f / fmaxf(s + 1.0f, 1e-8f);
        float Hp = 0.0f, Hq = 0.0f;
        #pragma unroll
        for (int j = 0; j < NBINS; ++j) {
            float oh = (j == b) ? 1.0f : 0.0f;
            float p  = c[j] * inv;
            float pp = (c[j] + oh) * invp;
            float lp = __log2f(p  + 1e-10f);
            float lq = __log2f(pp + 1e-10f);
            Hp -= p * lp; Hq -= pp * lq;
            ig += pp * (lq - lp);
            out[(size_t)3 * dim + 2 + (size_t)i * NBINS + j] =
                fmaxf(c[j] * 0.95f + oh * 0.05f, 0.01f);
        }
        ig = fmaxf(ig, 0.0f);
        out[i] = ig;
        out[(size_t)dim     + 1 + i] = Hp;
        out[(size_t)2 * dim + 1 + i] = Hq;
    }

    // ---- deterministic block reduction of info_gain ----
    const unsigned FULL_M = 0xffffffffu;
    #pragma unroll
    for (int o = 16; o > 0; o >>= 1)
        ig += __shfl_down_sync(FULL_M, ig, o);

    __shared__ float ws[THREADS / 32];
    int lane = t & 31;
    int w    = t >> 5;
    if (lane == 0) ws[w] = ig;
    __syncthreads();
    if (w == 0) {
        float v = (lane < THREADS / 32) ? ws[lane] : 0.0f;
        #pragma unroll
        for (int o = 4; o > 0; o >>= 1)
            v += __shfl_down_sync(FULL_M, v, o);
        if (lane == 0) g_partials[blockIdx.x] = v;
    }

    // ---- last-block final reduction ----
    __shared__ bool is_last;
    __threadfence();
    if (t == 0) {
        unsigned ticket = atomicAdd(&g_counter, 1u);
        is_last = (ticket == (unsigned)(nblocks - 1));
    }
    __syncthreads();

    if (is_last) {
        __threadfence();
        __shared__ double sh[THREADS];
        double a = 0.0;
        for (int p = t; p < nblocks; p += THREADS)   // fixed order
            a += (double)g_partials[p];
        sh[t] = a;
        __syncthreads();
        #pragma unroll
        for (int o = THREADS / 2; o > 0; o >>= 1) {
            if (t < o) sh[t] += sh[t + o];
            __syncthreads();
        }
        if (t == 0) {
            float mean = (float)(sh[0] / (double)dim);
            out[dim] = mean;
            float z = mean * 50.0f - 1.0f;
            out[(size_t)3 * dim + 1] = 1.0f / (1.0f + expf(-z));
            g_counter = 0;   // reset for next graph replay
        }
    }
}

extern "C" void kernel_launch(void* const* d_in, const int* in_sizes, int n_in,
                              void* d_out, int out_size)
{
    const float* obs    = (const float*)d_in[0];
    const float* counts = (const float*)d_in[1];
    float* out = (float*)d_out;

    int dim  = in_sizes[1] / NBINS;
    int rows = in_sizes[0] / dim;
    int nb   = (dim + THREADS - 1) / THREADS;

    ep_fused_kernel<<<nb, THREADS>>>(obs, counts, out, dim, rows,
                                     1.0f / (float)rows, nb);
}

// round 14
// speedup vs baseline: 1.1516x; 1.0577x over previous
#include <cuda_runtime.h>

#define THREADS 256
#define NBINS 16
#define MAXGRID 592          // ~4 persistent blocks per SM on 148 SMs

__device__ float g_partials[32768];
__device__ unsigned int g_counter = 0;

// Scalar fallback for tail dims (unused when dim % 256 == 0).
__device__ float ep_scalar_dim(const float* __restrict__ obs,
                               const float* __restrict__ counts,
                               float* __restrict__ out,
                               int dim, int rows, float inv_rows, int i)
{
    float m = 0.0f;
    for (int r = 0; r < rows; ++r) m += obs[(size_t)r * dim + i];
    m *= inv_rows;
    float sgm = 1.0f / (1.0f + __expf(-m));
    int b = (int)(sgm * (float)(NBINS - 1));
    b = b < 0 ? 0 : (b > NBINS - 1 ? NBINS - 1 : b);

    float c[NBINS];
    #pragma unroll
    for (int j = 0; j < NBINS; ++j) c[j] = counts[(size_t)i * NBINS + j];
    float s = 0.0f;
    #pragma unroll
    for (int j = 0; j < NBINS; ++j) s += c[j];
    float inv  = 1.0f / fmaxf(s,        1e-8f);
    float invp = 1.0f / fmaxf(s + 1.0f, 1e-8f);
    float Hp = 0.0f, Hq = 0.0f, ig = 0.0f;
    #pragma unroll
    for (int j = 0; j < NBINS; ++j) {
        float oh = (j == b) ? 1.0f : 0.0f;
        float p  = c[j] * inv;
        float pp = (c[j] + oh) * invp;
        float lp = __log2f(p  + 1e-10f);
        float lq = __log2f(pp + 1e-10f);
        Hp -= p * lp; Hq -= pp * lq;
        ig += pp * (lq - lp);
        out[(size_t)3 * dim + 2 + (size_t)i * NBINS + j] =
            fmaxf(c[j] * 0.95f + oh * 0.05f, 0.01f);
    }
    ig = fmaxf(ig, 0.0f);
    out[i] = ig;
    out[(size_t)dim     + 1 + i] = Hp;
    out[(size_t)2 * dim + 1 + i] = Hq;
    return ig;
}

__global__ void __launch_bounds__(THREADS) ep_pipe_kernel(
    const float* __restrict__ obs,      // (rows, dim)
    const float* __restrict__ counts,   // (dim, 16)
    float* __restrict__ out,            // concatenated outputs
    int dim, int rows, float inv_rows, int nblocks, int ntiles)
{
    // Double-buffered padded staging: dim d owns float4 slots [d*5, d*5+4);
    // slot d*5+4 is padding (conflict-free LDS.128 per-row reads).
    __shared__ float4 s4[2][THREADS * 5];   // 40 KB
    __shared__ int    sb[2][THREADS];

    const int t = threadIdx.x;
    float igacc = 0.0f;

    int tile = blockIdx.x;
    const int step = gridDim.x;

    // register pipeline state (loads for the *next* tile to stage)
    float  o0, o1, o2, o3, o4, o5, o6, o7;
    float4 cv0, cv1, cv2, cv3;

    // ---------------- prologue: load + stage tile0 ----------------
    if (tile < ntiles) {
        const int base = tile * THREADS;
        const float* op = obs + base + t;
        const float4* cin = (const float4*)counts + (size_t)base * 4 + t;
        if (rows == 8) {
            o0 = __ldcs(op);
            o1 = __ldcs(op + (size_t)dim);
            o2 = __ldcs(op + (size_t)2 * dim);
            o3 = __ldcs(op + (size_t)3 * dim);
            o4 = __ldcs(op + (size_t)4 * dim);
            o5 = __ldcs(op + (size_t)5 * dim);
            o6 = __ldcs(op + (size_t)6 * dim);
            o7 = __ldcs(op + (size_t)7 * dim);
        } else {
            o0 = 0.0f;
            for (int r = 0; r < rows; ++r) o0 += __ldcs(op + (size_t)r * dim);
            o1 = o2 = o3 = o4 = o5 = o6 = o7 = 0.0f;
        }
        cv0 = __ldcs(cin);
        cv1 = __ldcs(cin + THREADS);
        cv2 = __ldcs(cin + 2 * THREADS);
        cv3 = __ldcs(cin + 3 * THREADS);

        // stage into buffer 0
        int idx0 = t, idx1 = t + THREADS, idx2 = t + 2 * THREADS, idx3 = t + 3 * THREADS;
        s4[0][(idx0 >> 2) * 5 + (idx0 & 3)] = cv0;
        s4[0][(idx1 >> 2) * 5 + (idx1 & 3)] = cv1;
        s4[0][(idx2 >> 2) * 5 + (idx2 & 3)] = cv2;
        s4[0][(idx3 >> 2) * 5 + (idx3 & 3)] = cv3;
        float m = (((o0 + o1) + (o2 + o3)) + ((o4 + o5) + (o6 + o7))) * inv_rows;
        float sgm = 1.0f / (1.0f + __expf(-m));
        int b = (int)(sgm * (float)(NBINS - 1));
        b = b < 0 ? 0 : (b > NBINS - 1 ? NBINS - 1 : b);
        sb[0][t] = b;
    }
    __syncthreads();

    // ---------------- pipelined main loop ----------------
    int cur = 0;
    while (tile < ntiles) {
        const int next_tile = tile + step;
        const bool have_next = (next_tile < ntiles);

        // 1) issue next tile's loads FIRST (overlap with compute below)
        if (have_next) {
            const int nbase = next_tile * THREADS;
            const float* op = obs + nbase + t;
            const float4* cin = (const float4*)counts + (size_t)nbase * 4 + t;
            if (rows == 8) {
                o0 = __ldcs(op);
                o1 = __ldcs(op + (size_t)dim);
                o2 = __ldcs(op + (size_t)2 * dim);
                o3 = __ldcs(op + (size_t)3 * dim);
                o4 = __ldcs(op + (size_t)4 * dim);
                o5 = __ldcs(op + (size_t)5 * dim);
                o6 = __ldcs(op + (size_t)6 * dim);
                o7 = __ldcs(op + (size_t)7 * dim);
            } else {
                o0 = 0.0f;
                for (int r = 0; r < rows; ++r) o0 += __ldcs(op + (size_t)r * dim);
                o1 = o2 = o3 = o4 = o5 = o6 = o7 = 0.0f;
            }
            cv0 = __ldcs(cin);
            cv1 = __ldcs(cin + THREADS);
            cv2 = __ldcs(cin + 2 * THREADS);
            cv3 = __ldcs(cin + 3 * THREADS);
        }

        // 2) compute + store current tile from smem[cur]
        {
            const int base = tile * THREADS;
            const int i = base + t;
            const int b = sb[cur][t];

            float c[NBINS];
            #pragma unroll
            for (int q = 0; q < 4; ++q) {
                float4 v = s4[cur][t * 5 + q];
                c[4*q+0] = v.x; c[4*q+1] = v.y; c[4*q+2] = v.z; c[4*q+3] = v.w;
            }

            float s = 0.0f;
            #pragma unroll
            for (int j = 0; j < NBINS; ++j) s += c[j];

            // log2(c/s + 1e-10) = log2(c + 1e-10*s) - log2(s)  (exact)
            const float tiny = 1e-10f * s;
            float T = 0.0f, cb = 0.0f, ubin = 0.0f;
            #pragma unroll
            for (int j = 0; j < NBINS; ++j) {
                float u = __log2f(c[j] + tiny);
                T += c[j] * u;
                if (j == b) { cb = c[j]; ubin = u; }
            }
            float ub  = __log2f(cb + 1.0f);
            float ls  = __log2f(s);
            float ls1 = __log2f(s + 1.0f);
            float inv  = 1.0f / s;
            float invp = 1.0f / (s + 1.0f);

            float Hp = ls  - T * inv;
            float Hq = ls1 - (T - cb * ubin + (cb + 1.0f) * ub) * invp;
            float ig = fmaxf((cb + 1.0f) * invp * (ub - ubin) - (ls1 - ls), 0.0f);

            __stcs(out + i, ig);
            __stcs(out + (size_t)dim     + 1 + i, Hp);
            __stcs(out + (size_t)2 * dim + 1 + i, Hq);
            igacc += ig;

            // coalesced new_counts stage-out (2048 float2 slots)
            const float2* s2 = (const float2*)s4[cur];
            float2* obase = (float2*)(out + (size_t)3 * dim + 2 + (size_t)base * NBINS);
            #pragma unroll
            for (int k = 0; k < 8; ++k) {
                int idx = t + k * THREADS;
                int d = idx >> 3, h = idx & 7;
                float2 cc = s2[d * 10 + h];
                int bd = sb[cur][d];
                float w0 = (2 * h     == bd) ? 0.05f : 0.0f;
                float w1 = (2 * h + 1 == bd) ? 0.05f : 0.0f;
                float2 r;
                r.x = fmaxf(cc.x * 0.95f + w0, 0.01f);
                r.y = fmaxf(cc.y * 0.95f + w1, 0.01f);
                __stcs(obase + idx, r);
            }
        }

        // 3) stage next tile into smem[1-cur]
        if (have_next) {
            const int nxt = 1 - cur;
            int idx0 = t, idx1 = t + THREADS, idx2 = t + 2 * THREADS, idx3 = t + 3 * THREADS;
            s4[nxt][(idx0 >> 2) * 5 + (idx0 & 3)] = cv0;
            s4[nxt][(idx1 >> 2) * 5 + (idx1 & 3)] = cv1;
            s4[nxt][(idx2 >> 2) * 5 + (idx2 & 3)] = cv2;
            s4[nxt][(idx3 >> 2) * 5 + (idx3 & 3)] = cv3;
            float m = (((o0 + o1) + (o2 + o3)) + ((o4 + o5) + (o6 + o7))) * inv_rows;
            float sgm = 1.0f / (1.0f + __expf(-m));
            int b = (int)(sgm * (float)(NBINS - 1));
            b = b < 0 ? 0 : (b > NBINS - 1 ? NBINS - 1 : b);
            sb[nxt][t] = b;
        }
        __syncthreads();   // one barrier per tile

        tile = next_tile;
        cur ^= 1;
    }

    // ---------------- scalar tail dims (dim % 256 != 0) ----------------
    for (int i = ntiles * THREADS + blockIdx.x * THREADS + t; i < dim;
         i += gridDim.x * THREADS)
        igacc += ep_scalar_dim(obs, counts, out, dim, rows, inv_rows, i);

    // ---------------- deterministic block reduction ----------------
    const unsigned FULL_M = 0xffffffffu;
    #pragma unroll
    for (int o = 16; o > 0; o >>= 1)
        igacc += __shfl_down_sync(FULL_M, igacc, o);

    __shared__ float ws[THREADS / 32];
    int lane = t & 31;
    int w    = t >> 5;
    if (lane == 0) ws[w] = igacc;
    __syncthreads();
    if (w == 0) {
        float v = (lane < THREADS / 32) ? ws[lane] : 0.0f;
        #pragma unroll
        for (int o = 4; o > 0; o >>= 1)
            v += __shfl_down_sync(FULL_M, v, o);
        if (lane == 0) g_partials[blockIdx.x] = v;
    }

    // ---------------- last-block final reduction ----------------
    __shared__ bool is_last;
    __threadfence();
    if (t == 0) {
        unsigned ticket = atomicAdd(&g_counter, 1u);
        is_last = (ticket == (unsigned)(nblocks - 1));
    }
    __syncthreads();

    if (is_last) {
        __threadfence();
        __shared__ double sh[THREADS];
        double a = 0.0;
        for (int p = t; p < nblocks; p += THREADS)   // fixed order
            a += (double)g_partials[p];
        sh[t] = a;
        __syncthreads();
        #pragma unroll
        for (int o = THREADS / 2; o > 0; o >>= 1) {
            if (t < o) sh[t] += sh[t + o];
            __syncthreads();
        }
        if (t == 0) {
            float mean = (float)(sh[0] / (double)dim);
            out[dim] = mean;
            float z = mean * 50.0f - 1.0f;
            out[(size_t)3 * dim + 1] = 1.0f / (1.0f + expf(-z));
            g_counter = 0;   // reset for next graph replay
        }
    }
}

extern "C" void kernel_launch(void* const* d_in, const int* in_sizes, int n_in,
                              void* d_out, int out_size)
{
    const float* obs    = (const float*)d_in[0];
    const float* counts = (const float*)d_in[1];
    float* out = (float*)d_out;

    int dim    = in_sizes[1] / NBINS;
    int rows   = in_sizes[0] / dim;
    int ntiles = dim / THREADS;                 // full tiles only
    int nb     = ntiles < 1 ? 1 : (ntiles < MAXGRID ? ntiles : MAXGRID);

    ep_pipe_kernel<<<nb, THREADS>>>(obs, counts, out, dim, rows,
                                    1.0f / (float)rows, nb, ntiles);
}